// round 6
// baseline (speedup 1.0000x reference)
#include <cuda_runtime.h>
#include <cstdint>

typedef unsigned long long u64;

#define IMG_W 512
#define IMG_H 512

// ---- f32x2 packed helpers ----
__device__ __forceinline__ u64 pack2(float lo, float hi) {
    u64 r;
    asm("mov.b64 %0, {%1, %2};"
        : "=l"(r) : "r"(__float_as_uint(lo)), "r"(__float_as_uint(hi)));
    return r;
}

__device__ __forceinline__ void fma2(u64& d, u64 a, u64 b) {
    asm("fma.rn.f32x2 %0, %1, %2, %0;" : "+l"(d) : "l"(a), "l"(b));
}

// (hi(a), lo(b)) -> odd-aligned sliding pair (2 MOVs in SASS).
__device__ __forceinline__ u64 pack_hl(u64 a, u64 b) {
    u64 d;
    asm("{\n\t"
        ".reg .b32 al, ah, bl, bh;\n\t"
        "mov.b64 {al, ah}, %1;\n\t"
        "mov.b64 {bl, bh}, %2;\n\t"
        "mov.b64 %0, {ah, bl};\n\t"
        "}" : "=l"(d) : "l"(a), "l"(b));
    return d;
}

// Thread: 4 output rows x 4 output cols, all math on f32x2 pairs.
// Block: 256 threads = 128 col-threads (512 cols) x 2 row groups (8 rows).
// Grid: (64 row tiles, 128 images).
// launch_bounds(256, 2): allow 128 regs/thread so the 25 broadcast weight
// pairs + 8 accumulator pairs stay register-resident as ALIGNED PAIRS --
// removes the per-FFMA2 pair-assembly MOV tax seen at regs=40.
__global__ __launch_bounds__(256, 2)
void conv5x5_f32x2_kernel(const float* __restrict__ X,
                          const float* __restrict__ K,
                          float* __restrict__ O) {
    const int tx   = threadIdx.x & 127;
    const int tg   = threadIdx.x >> 7;
    const int col  = tx << 2;                        // multiple of 4 -> 16B aligned
    const int img  = blockIdx.y;
    const int row0 = (blockIdx.x << 3) + (tg << 2);

    // Weights: vector loads, broadcast-pack (w,w) x25, kept live in pairs.
    u64 wp[25];
    {
        const float4* K4 = reinterpret_cast<const float4*>(K);
        #pragma unroll
        for (int i = 0; i < 6; i++) {
            float4 v = __ldg(K4 + i);
            wp[4*i+0] = pack2(v.x, v.x);
            wp[4*i+1] = pack2(v.y, v.y);
            wp[4*i+2] = pack2(v.z, v.z);
            wp[4*i+3] = pack2(v.w, v.w);
        }
        float w24 = __ldg(K + 24);
        wp[24] = pack2(w24, w24);
    }

    const float* in = X + (size_t)img * (IMG_W * IMG_H);

    const bool has_left  = (col >= 2);        // row-invariant halo predicates
    const bool has_right = (col + 4 < IMG_W);

    u64 acc[4][2];
    #pragma unroll
    for (int ro = 0; ro < 4; ro++) { acc[ro][0] = 0ull; acc[ro][1] = 0ull; }

    #pragma unroll
    for (int lr = 0; lr < 8; lr++) {
        const int r = row0 - 2 + lr;                  // input row (warp-uniform test)
        u64 p0, p2, p4, p6;                           // even-aligned pairs, direct from loads
        if (r >= 0 && r < IMG_H) {
            const float* rp = in + (size_t)r * IMG_W;
            p0 = has_left  ? *reinterpret_cast<const u64*>(rp + col - 2) : 0ull;
            ulonglong2 m = *reinterpret_cast<const ulonglong2*>(rp + col);   // LDG.128
            p2 = m.x;
            p4 = m.y;
            p6 = has_right ? *reinterpret_cast<const u64*>(rp + col + 4) : 0ull;
        } else {
            p0 = p2 = p4 = p6 = 0ull;
        }
        // Odd-aligned pairs: 3 packs (6 MOVs) per row.
        u64 p1 = pack_hl(p0, p2);
        u64 p3 = pack_hl(p2, p4);
        u64 p5 = pack_hl(p4, p6);
        u64 p[7] = {p0, p1, p2, p3, p4, p5, p6};

        // Input row r feeds output rows ro with kr = lr - ro in [0,4]
        #pragma unroll
        for (int ro = 0; ro < 4; ro++) {
            const int kr = lr - ro;
            if (kr < 0 || kr > 4) continue;
            #pragma unroll
            for (int kc = 0; kc < 5; kc++) {
                fma2(acc[ro][0], p[kc],     wp[kr*5 + kc]);  // outputs (col, col+1)
                fma2(acc[ro][1], p[kc + 2], wp[kr*5 + kc]);  // outputs (col+2, col+3)
            }
        }
    }

    float* op = O + (size_t)img * (IMG_W * IMG_H) + (size_t)row0 * IMG_W + col;
    #pragma unroll
    for (int ro = 0; ro < 4; ro++) {
        ulonglong2 v;
        v.x = acc[ro][0];
        v.y = acc[ro][1];
        *reinterpret_cast<ulonglong2*>(op + (size_t)ro * IMG_W) = v;  // STG.128
    }
}

extern "C" void kernel_launch(void* const* d_in, const int* in_sizes, int n_in,
                              void* d_out, int out_size) {
    const float* X = (const float*)d_in[0];   // (4,32,512,512) f32
    const float* K = (const float*)d_in[1];   // (5,5) f32
    float* O = (float*)d_out;                 // (4,32,512,512) f32
    (void)in_sizes; (void)n_in; (void)out_size;  // stride=1, padding=2 fixed

    dim3 grid(IMG_H / 8, 4 * 32);             // 64 row tiles x 128 images
    conv5x5_f32x2_kernel<<<grid, 256>>>(X, K, O);
}

// round 7
// speedup vs baseline: 2.4864x; 2.4864x over previous
#include <cuda_runtime.h>
#include <cstdint>

typedef unsigned long long u64;

#define IMG_W 512
#define IMG_H 512
#define FULL 0xFFFFFFFFu

// ---- f32x2 packed helpers ----
__device__ __forceinline__ u64 pack2(float lo, float hi) {
    u64 r;
    asm("mov.b64 %0, {%1, %2};"
        : "=l"(r) : "r"(__float_as_uint(lo)), "r"(__float_as_uint(hi)));
    return r;
}

__device__ __forceinline__ void fma2(u64& d, u64 a, u64 b) {
    asm("fma.rn.f32x2 %0, %1, %2, %0;" : "+l"(d) : "l"(a), "l"(b));
}

// (hi(a), lo(b)) -> odd-aligned sliding pair (2 MOVs in SASS).
__device__ __forceinline__ u64 pack_hl(u64 a, u64 b) {
    u64 d;
    asm("{\n\t"
        ".reg .b32 al, ah, bl, bh;\n\t"
        "mov.b64 {al, ah}, %1;\n\t"
        "mov.b64 {bl, bh}, %2;\n\t"
        "mov.b64 %0, {ah, bl};\n\t"
        "}" : "=l"(d) : "l"(a), "l"(b));
    return d;
}

// Thread: 4 output rows x 4 output cols. Block: 256 = 128 col-threads x 2 row
// groups. Each warp's 32 lanes cover 128 contiguous columns, so halo pairs
// live in the neighbor lane's LDG.128 registers -> fetch via SHFL, not LDG.
// Only lanes 0/31 of a warp need a (predicated) edge LDG.64.
__global__ __launch_bounds__(256)
void conv5x5_f32x2_kernel(const float* __restrict__ X,
                          const float* __restrict__ K,
                          float* __restrict__ O) {
    const int tx   = threadIdx.x & 127;
    const int tg   = threadIdx.x >> 7;
    const int lid  = threadIdx.x & 31;
    const int col  = tx << 2;                        // 16B-aligned output col base
    const int img  = blockIdx.y;
    const int row0 = (blockIdx.x << 3) + (tg << 2);

    // Broadcast-packed weights (w,w) x25.
    u64 wp[25];
    {
        const float4* K4 = reinterpret_cast<const float4*>(K);
        #pragma unroll
        for (int i = 0; i < 6; i++) {
            float4 v = __ldg(K4 + i);
            wp[4*i+0] = pack2(v.x, v.x);
            wp[4*i+1] = pack2(v.y, v.y);
            wp[4*i+2] = pack2(v.z, v.z);
            wp[4*i+3] = pack2(v.w, v.w);
        }
        float w24 = __ldg(K + 24);
        wp[24] = pack2(w24, w24);
    }

    const float* in = X + (size_t)img * (IMG_W * IMG_H);

    const bool edgeL = (lid == 0)  && (col >= 2);        // lane-0 left edge LDG
    const bool edgeR = (lid == 31) && (col + 4 < IMG_W); // lane-31 right edge LDG

    u64 acc[4][2];
    #pragma unroll
    for (int ro = 0; ro < 4; ro++) { acc[ro][0] = 0ull; acc[ro][1] = 0ull; }

    // --- load stage for one input row ---
    u64 cm0, cm1, ce0, ce6;        // current row: main pair regs + edge regs
    {
        const int r = row0 - 2;
        cm0 = cm1 = ce0 = ce6 = 0ull;
        if (r >= 0) {              // r < IMG_H always true for first row
            const float* rp = in + (size_t)r * IMG_W;
            ulonglong2 m = *reinterpret_cast<const ulonglong2*>(rp + col);
            cm0 = m.x; cm1 = m.y;
            if (edgeL) ce0 = *reinterpret_cast<const u64*>(rp + col - 2);
            if (edgeR) ce6 = *reinterpret_cast<const u64*>(rp + col + 4);
        }
    }

    #pragma unroll
    for (int lr = 0; lr < 8; lr++) {
        // Prefetch next row before computing current one.
        u64 nm0 = 0ull, nm1 = 0ull, ne0 = 0ull, ne6 = 0ull;
        if (lr < 7) {
            const int rn = row0 - 1 + lr;
            if (rn >= 0 && rn < IMG_H) {
                const float* rp = in + (size_t)rn * IMG_W;
                ulonglong2 m = *reinterpret_cast<const ulonglong2*>(rp + col);
                nm0 = m.x; nm1 = m.y;
                if (edgeL) ne0 = *reinterpret_cast<const u64*>(rp + col - 2);
                if (edgeR) ne6 = *reinterpret_cast<const u64*>(rp + col + 4);
            }
        }

        // Halo pairs via intra-warp shuffle of the 128-bit load halves.
        u64 p0 = __shfl_up_sync(FULL, cm1, 1);    // lane l-1's (x[col-2],x[col-1])
        if (lid == 0)  p0 = ce0;                  // warp edge: own LDG (or 0)
        u64 p6 = __shfl_down_sync(FULL, cm0, 1);  // lane l+1's (x[col+4],x[col+5])
        if (lid == 31) p6 = ce6;
        u64 p2 = cm0, p4 = cm1;
        u64 p1 = pack_hl(p0, p2);
        u64 p3 = pack_hl(p2, p4);
        u64 p5 = pack_hl(p4, p6);
        u64 p[7] = {p0, p1, p2, p3, p4, p5, p6};

        // Input row feeds output rows ro with kr = lr - ro in [0,4].
        #pragma unroll
        for (int ro = 0; ro < 4; ro++) {
            const int kr = lr - ro;
            if (kr < 0 || kr > 4) continue;
            #pragma unroll
            for (int kc = 0; kc < 5; kc++) {
                fma2(acc[ro][0], p[kc],     wp[kr*5 + kc]);
                fma2(acc[ro][1], p[kc + 2], wp[kr*5 + kc]);
            }
        }

        cm0 = nm0; cm1 = nm1; ce0 = ne0; ce6 = ne6;
    }

    float* op = O + (size_t)img * (IMG_W * IMG_H) + (size_t)row0 * IMG_W + col;
    #pragma unroll
    for (int ro = 0; ro < 4; ro++) {
        ulonglong2 v;
        v.x = acc[ro][0];
        v.y = acc[ro][1];
        *reinterpret_cast<ulonglong2*>(op + (size_t)ro * IMG_W) = v;  // STG.128
    }
}

extern "C" void kernel_launch(void* const* d_in, const int* in_sizes, int n_in,
                              void* d_out, int out_size) {
    const float* X = (const float*)d_in[0];   // (4,32,512,512) f32
    const float* K = (const float*)d_in[1];   // (5,5) f32
    float* O = (float*)d_out;                 // (4,32,512,512) f32
    (void)in_sizes; (void)n_in; (void)out_size;  // stride=1, padding=2 fixed

    dim3 grid(IMG_H / 8, 4 * 32);             // 64 row tiles x 128 images
    conv5x5_f32x2_kernel<<<grid, 256>>>(X, K, O);
}

// round 8
// speedup vs baseline: 2.7159x; 1.0923x over previous
#include <cuda_runtime.h>
#include <cstdint>

typedef unsigned long long u64;

#define IMG_W 512
#define IMG_H 512

#define TILE_OROWS 8            // output rows per CTA
#define SROWS 12                // input rows staged (8 + 4 halo)
#define SCOLS 516               // padded cols: cpad = c + 2, c in [-2, 513]
#define SSTRIDE 520             // floats per smem row (8B-aligned stride)

// ---- f32x2 packed helpers ----
__device__ __forceinline__ u64 pack2(float lo, float hi) {
    u64 r;
    asm("mov.b64 %0, {%1, %2};"
        : "=l"(r) : "r"(__float_as_uint(lo)), "r"(__float_as_uint(hi)));
    return r;
}

__device__ __forceinline__ void fma2(u64& d, u64 a, u64 b) {
    asm("fma.rn.f32x2 %0, %1, %2, %0;" : "+l"(d) : "l"(a), "l"(b));
}

// (hi(a), lo(b)) -> odd-aligned sliding pair (2 MOVs in SASS).
__device__ __forceinline__ u64 pack_hl(u64 a, u64 b) {
    u64 d;
    asm("{\n\t"
        ".reg .b32 al, ah, bl, bh;\n\t"
        "mov.b64 {al, ah}, %1;\n\t"
        "mov.b64 {bl, bh}, %2;\n\t"
        "mov.b64 %0, {ah, bl};\n\t"
        "}" : "=l"(d) : "l"(a), "l"(b));
    return d;
}

// CTA: 256 threads. Stage a 12-row x 516-col zero-padded input tile in smem
// (burst of 6 independent LDG.128 per thread = high MLP), then feed ALL conv
// FMAs from LDS.64 (29-cycle latency) so the FFMA2 stream never waits on
// DRAM/L2 scoreboards. Thread computes 4 out rows x 4 out cols.
__global__ __launch_bounds__(256)
void conv5x5_smem_kernel(const float* __restrict__ X,
                         const float* __restrict__ K,
                         float* __restrict__ O) {
    __shared__ float smem[SROWS * SSTRIDE];

    const int tid  = threadIdx.x;
    const int tx   = tid & 127;
    const int tg   = tid >> 7;
    const int col  = tx << 2;
    const int img  = blockIdx.y;
    const int row0 = blockIdx.x << 3;          // CTA's first output row

    const float* in = X + (size_t)img * (IMG_W * IMG_H);

    // ---- Stage 1: burst-load tile (rows row0-2 .. row0+9), zero-filled OOB.
    // 12 rows x 128 float4 = 1536 quads; 256 threads x 6 iters.
    #pragma unroll
    for (int i = 0; i < 6; i++) {
        const int q  = tid + (i << 8);
        const int r  = q >> 7;                  // 0..11
        const int c  = (q & 127) << 2;          // 0..508
        const int gr = row0 - 2 + r;
        float4 v = make_float4(0.f, 0.f, 0.f, 0.f);
        if (gr >= 0 && gr < IMG_H)
            v = *reinterpret_cast<const float4*>(in + (size_t)gr * IMG_W + c);
        // store shifted by +2 cols (cpad = c + 2): two 8B-aligned STS.64
        float* sp = smem + r * SSTRIDE + c + 2;
        *reinterpret_cast<u64*>(sp)     = pack2(v.x, v.y);
        *reinterpret_cast<u64*>(sp + 2) = pack2(v.z, v.w);
    }
    // halo columns: cpad {0,1} and {514,515} are always zero
    if (tid < 24) {
        const int r    = tid < 12 ? tid : tid - 12;
        const int cpad = tid < 12 ? 0 : 514;
        *reinterpret_cast<u64*>(smem + r * SSTRIDE + cpad) = 0ull;
    }

    // Broadcast-packed weights (w,w) x25 (independent of smem fill).
    u64 wp[25];
    {
        const float4* K4 = reinterpret_cast<const float4*>(K);
        #pragma unroll
        for (int i = 0; i < 6; i++) {
            float4 v = __ldg(K4 + i);
            wp[4*i+0] = pack2(v.x, v.x);
            wp[4*i+1] = pack2(v.y, v.y);
            wp[4*i+2] = pack2(v.z, v.z);
            wp[4*i+3] = pack2(v.w, v.w);
        }
        float w24 = __ldg(K + 24);
        wp[24] = pack2(w24, w24);
    }

    __syncthreads();

    // ---- Stage 2: conv from smem. Thread's output rows: row0 + tg*4 + 0..3.
    u64 acc[4][2];
    #pragma unroll
    for (int ro = 0; ro < 4; ro++) { acc[ro][0] = 0ull; acc[ro][1] = 0ull; }

    #pragma unroll
    for (int lr = 0; lr < 8; lr++) {
        const float* sp = smem + ((tg << 2) + lr) * SSTRIDE + col;  // cpad base
        // even-aligned pairs straight from LDS.64
        u64 p0 = *reinterpret_cast<const u64*>(sp);       // (x[c-2],x[c-1])
        u64 p2 = *reinterpret_cast<const u64*>(sp + 2);   // (x[c],  x[c+1])
        u64 p4 = *reinterpret_cast<const u64*>(sp + 4);   // (x[c+2],x[c+3])
        u64 p6 = *reinterpret_cast<const u64*>(sp + 6);   // (x[c+4],x[c+5])
        u64 p1 = pack_hl(p0, p2);
        u64 p3 = pack_hl(p2, p4);
        u64 p5 = pack_hl(p4, p6);
        u64 p[7] = {p0, p1, p2, p3, p4, p5, p6};

        // input row lr feeds output rows ro with kr = lr - ro in [0,4]
        #pragma unroll
        for (int ro = 0; ro < 4; ro++) {
            const int kr = lr - ro;
            if (kr < 0 || kr > 4) continue;
            #pragma unroll
            for (int kc = 0; kc < 5; kc++) {
                fma2(acc[ro][0], p[kc],     wp[kr*5 + kc]);  // (col, col+1)
                fma2(acc[ro][1], p[kc + 2], wp[kr*5 + kc]);  // (col+2, col+3)
            }
        }
    }

    float* op = O + (size_t)img * (IMG_W * IMG_H)
                  + (size_t)(row0 + (tg << 2)) * IMG_W + col;
    #pragma unroll
    for (int ro = 0; ro < 4; ro++) {
        ulonglong2 v;
        v.x = acc[ro][0];
        v.y = acc[ro][1];
        *reinterpret_cast<ulonglong2*>(op + (size_t)ro * IMG_W) = v;  // STG.128
    }
}

extern "C" void kernel_launch(void* const* d_in, const int* in_sizes, int n_in,
                              void* d_out, int out_size) {
    const float* X = (const float*)d_in[0];   // (4,32,512,512) f32
    const float* K = (const float*)d_in[1];   // (5,5) f32
    float* O = (float*)d_out;                 // (4,32,512,512) f32
    (void)in_sizes; (void)n_in; (void)out_size;  // stride=1, padding=2 fixed

    dim3 grid(IMG_H / TILE_OROWS, 4 * 32);    // 64 row tiles x 128 images
    conv5x5_smem_kernel<<<grid, 256>>>(X, K, O);
}